// round 15
// baseline (speedup 1.0000x reference)
#include <cuda_runtime.h>

// N=65536, D=512, C=1000. CONVERGED KERNEL (R13 structure, best measured).
// Warp-per-row, plain float4 x stream + __ldg w gather, 256 thr x 8192
// blocks, fused deterministic last-block-done finish.
//
// Evidence for convergence: kernel moves ~140MB at 4.56TB/s = within 0.5% of
// the DRAM-bytes floor at the platform's measured operating point. Three
// independent load mechanisms (register LDG @ 89-93% occ, per-warp cp.async
// rings, UBLKCP/TMA-path bulk copies with ~190KB/SM in flight) all converge
// at 4.0-4.6 TB/s with no pipe saturated -> effective HBM ceiling for this
// read-dominant mix on GB300 @NAT. Bytes are irreducible (fp32 x read once).
// Larger blocks (R14), multi-row warps (R2/R3), class binning (R6-R9), and
// evict hints (R11) all measured slower.

#define N_ROWS   65536
#define D_DIM    512
#define THREADS  256
#define WARPS_PER_BLOCK 8
#define NBLOCKS  (N_ROWS / WARPS_PER_BLOCK)   // 8192

__device__ float g_partial[NBLOCKS];
__device__ int   g_count;   // zero-init; last block resets each call

__global__ __launch_bounds__(THREADS) void center_loss_r1f(
    const float* __restrict__ x,
    const float* __restrict__ w,
    const int*   __restrict__ t,
    float* __restrict__ out)
{
    const int tid  = threadIdx.x;
    const int wid  = tid >> 5;
    const int lane = tid & 31;
    const int row  = blockIdx.x * WARPS_PER_BLOCK + wid;

    const float4* xr = reinterpret_cast<const float4*>(x + (size_t)row * D_DIM);
    const int cls = __ldg(&t[row]);
    const float4* wr = reinterpret_cast<const float4*>(w + (size_t)cls * D_DIM);

    float acc = 0.0f;
    // 512 floats / 32 lanes = 4 float4 per lane
    #pragma unroll
    for (int i = 0; i < 4; i++) {
        float4 a = xr[lane + i * 32];
        float4 b = __ldg(&wr[lane + i * 32]);
        float d0 = a.x - b.x;
        float d1 = a.y - b.y;
        float d2 = a.z - b.z;
        float d3 = a.w - b.w;
        acc = fmaf(d0, d0, acc);
        acc = fmaf(d1, d1, acc);
        acc = fmaf(d2, d2, acc);
        acc = fmaf(d3, d3, acc);
    }

    // warp reduce
    #pragma unroll
    for (int o = 16; o > 0; o >>= 1)
        acc += __shfl_xor_sync(0xFFFFFFFFu, acc, o);

    __shared__ float s[WARPS_PER_BLOCK];
    if (lane == 0)
        s[wid] = sqrtf(acc + 1e-6f);
    __syncthreads();

    __shared__ bool is_last;
    if (tid == 0) {
        float v = 0.0f;
        #pragma unroll
        for (int i = 0; i < WARPS_PER_BLOCK; i++) v += s[i];
        g_partial[blockIdx.x] = v;
        __threadfence();
        int old = atomicAdd(&g_count, 1);
        is_last = (old == NBLOCKS - 1);
    }
    __syncthreads();

    if (is_last) {
        // deterministic reduce over 8192 partials with 256 threads (32 each)
        float v = 0.0f;
        #pragma unroll
        for (int i = 0; i < NBLOCKS / THREADS; i++)
            v += g_partial[tid + i * THREADS];
        #pragma unroll
        for (int o = 16; o > 0; o >>= 1)
            v += __shfl_xor_sync(0xFFFFFFFFu, v, o);
        __shared__ float fs[WARPS_PER_BLOCK];
        if (lane == 0) fs[wid] = v;
        __syncthreads();
        if (tid < 32) {
            float u = (lane < WARPS_PER_BLOCK) ? fs[lane] : 0.0f;
            #pragma unroll
            for (int o = 16; o > 0; o >>= 1)
                u += __shfl_xor_sync(0xFFFFFFFFu, u, o);
            if (tid == 0) {
                out[0] = u * (1.0f / (float)N_ROWS);
                g_count = 0;   // reset for next graph replay
            }
        }
    }
}

extern "C" void kernel_launch(void* const* d_in, const int* in_sizes, int n_in,
                              void* d_out, int out_size)
{
    const float* x = (const float*)d_in[0];   // [N, D] fp32
    const float* w = (const float*)d_in[1];   // [C, D] fp32
    const int*   t = (const int*)d_in[2];     // [N] int32
    float* out = (float*)d_out;

    center_loss_r1f<<<NBLOCKS, THREADS>>>(x, w, t, out);
}

// round 16
// speedup vs baseline: 1.3100x; 1.3100x over previous
#include <cuda_runtime.h>

// N=65536, D=512, C=1000. CONVERGED KERNEL — byte-exact R13 (best measured:
// 31.2us). Warp-per-row, plain float4 x stream + __ldg w gather, 256 thr x
// 8192 blocks, fused deterministic last-block-done finish.
//
// R15 measured 41.4us on near-identical source with HBM at 3.5TB/s and
// HIGHER issue% — a DVFS/noisy-neighbor operating-point shift, not a code
// effect (the only delta, __ldg on the scalar t load, cannot cost 10us).
// Run-to-run variance at the memory floor on this @NAT part is +/-20-30%.
// All structural alternatives measured slower: multi-row warps (R2/R3),
// block-sync and per-warp cp.async pipelines (R4/R5), class binning
// (R6-R9), evict_last hints (R10/R11), UBLKCP bulk pipeline (R12), 512-thr
// blocks (R14). Kernel moves ~140MB within 0.5% of the DRAM-bytes floor at
// the best observed operating point (4.56TB/s).

#define N_ROWS   65536
#define D_DIM    512
#define THREADS  256
#define WARPS_PER_BLOCK 8
#define NBLOCKS  (N_ROWS / WARPS_PER_BLOCK)   // 8192

__device__ float g_partial[NBLOCKS];
__device__ int   g_count;   // zero-init; last block resets each call

__global__ __launch_bounds__(THREADS) void center_loss_r1f(
    const float* __restrict__ x,
    const float* __restrict__ w,
    const int*   __restrict__ t,
    float* __restrict__ out)
{
    const int tid  = threadIdx.x;
    const int wid  = tid >> 5;
    const int lane = tid & 31;
    const int row  = blockIdx.x * WARPS_PER_BLOCK + wid;

    const float4* xr = reinterpret_cast<const float4*>(x + (size_t)row * D_DIM);
    const int cls = t[row];
    const float4* wr = reinterpret_cast<const float4*>(w + (size_t)cls * D_DIM);

    float acc = 0.0f;
    // 512 floats / 32 lanes = 4 float4 per lane
    #pragma unroll
    for (int i = 0; i < 4; i++) {
        float4 a = xr[lane + i * 32];
        float4 b = __ldg(&wr[lane + i * 32]);
        float d0 = a.x - b.x;
        float d1 = a.y - b.y;
        float d2 = a.z - b.z;
        float d3 = a.w - b.w;
        acc = fmaf(d0, d0, acc);
        acc = fmaf(d1, d1, acc);
        acc = fmaf(d2, d2, acc);
        acc = fmaf(d3, d3, acc);
    }

    // warp reduce
    #pragma unroll
    for (int o = 16; o > 0; o >>= 1)
        acc += __shfl_xor_sync(0xFFFFFFFFu, acc, o);

    __shared__ float s[WARPS_PER_BLOCK];
    if (lane == 0)
        s[wid] = sqrtf(acc + 1e-6f);
    __syncthreads();

    __shared__ bool is_last;
    if (tid == 0) {
        float v = 0.0f;
        #pragma unroll
        for (int i = 0; i < WARPS_PER_BLOCK; i++) v += s[i];
        g_partial[blockIdx.x] = v;
        __threadfence();
        int old = atomicAdd(&g_count, 1);
        is_last = (old == NBLOCKS - 1);
    }
    __syncthreads();

    if (is_last) {
        // deterministic reduce over 8192 partials with 256 threads (32 each)
        float v = 0.0f;
        #pragma unroll
        for (int i = 0; i < NBLOCKS / THREADS; i++)
            v += g_partial[tid + i * THREADS];
        #pragma unroll
        for (int o = 16; o > 0; o >>= 1)
            v += __shfl_xor_sync(0xFFFFFFFFu, v, o);
        __shared__ float fs[WARPS_PER_BLOCK];
        if (lane == 0) fs[wid] = v;
        __syncthreads();
        if (tid < 32) {
            float u = (lane < WARPS_PER_BLOCK) ? fs[lane] : 0.0f;
            #pragma unroll
            for (int o = 16; o > 0; o >>= 1)
                u += __shfl_xor_sync(0xFFFFFFFFu, u, o);
            if (tid == 0) {
                out[0] = u * (1.0f / (float)N_ROWS);
                g_count = 0;   // reset for next graph replay
            }
        }
    }
}

extern "C" void kernel_launch(void* const* d_in, const int* in_sizes, int n_in,
                              void* d_out, int out_size)
{
    const float* x = (const float*)d_in[0];   // [N, D] fp32
    const float* w = (const float*)d_in[1];   // [C, D] fp32
    const int*   t = (const int*)d_in[2];     // [N] int32
    float* out = (float*)d_out;

    center_loss_r1f<<<NBLOCKS, THREADS>>>(x, w, t, out);
}